// round 6
// baseline (speedup 1.0000x reference)
#include <cuda_runtime.h>
#include <cuda_bf16.h>
#include <math.h>

#define BATCH   256
#define NEI     128
#define NRELS   5000
#define NSUP    32
#define DIM     128
#define TOPK    64
#define NCAND   8192

#define OFF_TN  0
#define OFF_TE  49152
#define OFF_PI  6340608
#define OFF_PN  6389760
#define OFF_AR  6438912

typedef unsigned long long ull;
typedef unsigned int u32;

__device__ float g_best[NRELS];
__device__ u32   g_rank[NRELS];
__device__ float g_relgi[NRELS * 384];
__device__ float g_wT[2][128 * 384];
__device__ int   g_e[3][BATCH * TOPK];
__device__ int   g_r[3][BATCH * TOPK];
__device__ int   g_p[3][BATCH * TOPK];

__device__ __forceinline__ ull f2pack(float lo, float hi) {
    ull d; asm("mov.b64 %0, {%1, %2};" : "=l"(d) : "f"(lo), "f"(hi)); return d;
}
__device__ __forceinline__ ull f2fma(ull a, ull b, ull c) {
    ull d; asm("fma.rn.f32x2 %0, %1, %2, %3;" : "=l"(d) : "l"(a), "l"(b), "l"(c)); return d;
}
__device__ __forceinline__ u32 ord32(float s) {
    u32 u = __float_as_uint(s);
    return (u & 0x80000000u) ? ~u : (u | 0x80000000u);
}

#define SH 20

// ================= device-side stage bodies ==================================

// ---- expand_big body (512 threads) ----
__device__ __forceinline__ void expand_big_body(const int2* __restrict__ edge,
                                                float* __restrict__ out,
                                                int step, int b) {
    __shared__ int s_cur[TOPK];
    __shared__ u32 s_p13[16], s_q13[16];
    __shared__ u32 s_bp, s_bq;
    __shared__ u32 wkeys[TOPK];
    __shared__ u32 s_wn;

    const int tid = threadIdx.x;
    const int wid = tid >> 5, lane = tid & 31;

    if (tid < TOPK) s_cur[tid] = g_e[step - 1][b * TOPK + tid];
    if (tid == 0) s_wn = 0;
    __syncthreads();

    u32 myk[16];
    #pragma unroll
    for (int m = 0; m < 16; ++m) {
        int i = tid + m * 512;
        int c = i >> 7, n = i & 127;
        int2 pr = __ldg(&edge[(long long)s_cur[c] * NEI + n]);
        myk[m] = (g_rank[pr.y] << 13) | (u32)i;
    }

    u32 K = 0;
    #pragma unroll 1
    for (int shift = 24; shift >= 0; shift -= 2) {
        u32 X1 = K | (1u << shift), X2 = K | (2u << shift), X3 = K | (3u << shift);
        u32 c1 = 0, c2 = 0, c3 = 0;
        #pragma unroll
        for (int m = 0; m < 16; ++m) {
            u32 k0 = myk[m];
            c1 += (k0 < X1); c2 += (k0 < X2); c3 += (k0 < X3);
        }
        u32 p = c1 | (c2 << 16);
        u32 q = c3;
        p = __reduce_add_sync(0xffffffffu, p);
        q = __reduce_add_sync(0xffffffffu, q);
        if (lane == 0) { s_p13[wid] = p; s_q13[wid] = q; }
        __syncthreads();
        if (tid < 32) {
            u32 vp = (tid < 16) ? s_p13[tid] : 0u;
            u32 vq = (tid < 16) ? s_q13[tid] : 0u;
            vp = __reduce_add_sync(0xffffffffu, vp);
            vq = __reduce_add_sync(0xffffffffu, vq);
            if (tid == 0) { s_bp = vp; s_bq = vq; }
        }
        __syncthreads();
        u32 n1 = s_bp & 0xffffu, n2 = s_bp >> 16, n3 = s_bq;
        u32 t = (n1 < TOPK) ? ((n2 < TOPK) ? ((n3 < TOPK) ? 3u : 2u) : 1u) : 0u;
        K |= t << shift;
        __syncthreads();
    }

    #pragma unroll
    for (int m = 0; m < 16; ++m) {
        if (myk[m] <= K) {
            u32 p = atomicAdd(&s_wn, 1u);
            wkeys[p] = myk[m];
        }
    }
    __syncthreads();

    if (tid < TOPK) {
        u32 my = wkeys[tid];
        int rank = 0;
        #pragma unroll 8
        for (int t = 0; t < TOPK; ++t) rank += (wkeys[t] < my);
        int i = my & (NCAND - 1);
        int c = i >> 7, n = i & 127;
        int ent = s_cur[c];
        int2 pr = __ldg(&edge[(long long)ent * NEI + n]);
        int j = rank;
        int gidx = b * TOPK + j;
        g_e[step][gidx] = pr.x;
        g_r[step][gidx] = pr.y;
        g_p[step][gidx] = c;
        out[OFF_TN + b * 192 + step * 64 + j] = (float)pr.x;
        if (step == 1) {
            out[OFF_PI + b * 192 + j]       = (float)c;
            out[OFF_PN + b * 192 + 64 + j]  = (float)g_e[0][b * TOPK + c];
            out[OFF_AR + b * 192 + j]       = (float)g_r[0][b * TOPK + c];
        } else {
            out[OFF_PI + b * 192 + 64 + j]  = (float)c;
            out[OFF_PN + b * 192 + 128 + j] = (float)g_e[1][b * TOPK + c];
            out[OFF_AR + b * 192 + 64 + j]  = (float)g_r[1][b * TOPK + c];
            out[OFF_AR + b * 192 + 128 + j] = (float)pr.y;
        }
    }
}

// ---- gru23 body (512 threads; matvec on tid<384) ----
__device__ __forceinline__ void gru23_body(const float* __restrict__ b_hh,
                                           float* __restrict__ out,
                                           int step, int b, int kb) {
    __shared__ __align__(16) float s_f[128 * SH];
    __shared__ __align__(16) float gh[16][384];
    __shared__ int s_p[16], s_rel[16];
    const int tid = threadIdx.x;
    if (tid < 16) {
        s_p[tid]   = g_p[step][b * TOPK + kb + tid];
        s_rel[tid] = g_r[step][b * TOPK + kb + tid];
    }
    __syncthreads();
    for (int idx = tid; idx < 16 * 128; idx += 512) {
        int n = idx >> 7, d = idx & 127;
        s_f[d * SH + n] = out[OFF_TE + ((b * 3 + (step - 1)) * 64 + s_p[n]) * 128 + d];
    }
    __syncthreads();

    if (tid < 384) {
        const int j = tid;
        const float bj = b_hh[j];
        ull acc[8];
        ull bj2 = f2pack(bj, bj);
        #pragma unroll
        for (int m = 0; m < 8; ++m) acc[m] = bj2;
        const float* wt = g_wT[1];
        #pragma unroll 4
        for (int k = 0; k < 128; ++k) {
            float w = __ldg(&wt[k * 384 + j]);
            ull wd = f2pack(w, w);
            const ulonglong2* row = (const ulonglong2*)&s_f[k * SH];
            ulonglong2 r0 = row[0], r1 = row[1], r2 = row[2], r3 = row[3];
            acc[0] = f2fma(wd, r0.x, acc[0]); acc[1] = f2fma(wd, r0.y, acc[1]);
            acc[2] = f2fma(wd, r1.x, acc[2]); acc[3] = f2fma(wd, r1.y, acc[3]);
            acc[4] = f2fma(wd, r2.x, acc[4]); acc[5] = f2fma(wd, r2.y, acc[5]);
            acc[6] = f2fma(wd, r3.x, acc[6]); acc[7] = f2fma(wd, r3.y, acc[7]);
        }
        #pragma unroll
        for (int m = 0; m < 8; ++m) {
            float2 v = *(float2*)&acc[m];
            gh[2 * m][j]     = v.x;
            gh[2 * m + 1][j] = v.y;
        }
    }
    __syncthreads();

    for (int idx = tid; idx < 16 * 128; idx += 512) {
        int n = idx >> 7, d = idx & 127;
        int r = s_rel[n];
        const float* gi = &g_relgi[r * 384];
        float ir = gi[d], iz = gi[128 + d], inn = gi[256 + d];
        float hr = gh[n][d], hz = gh[n][128 + d], hn = gh[n][256 + d];
        float hprev = s_f[d * SH + n];
        float rg = 1.f / (1.f + expf(-(ir + hr)));
        float z  = 1.f / (1.f + expf(-(iz + hz)));
        float nn = tanhf(inn + rg * hn);
        out[OFF_TE + ((b * 3 + step) * 64 + kb + n) * 128 + d] = (1.f - z) * nn + z * hprev;
    }
}

// ================= fused kernels =============================================

// K1: blocks [0,96): weight transpose; [96,106): best[]
__global__ void __launch_bounds__(512) k1_kernel(const float* __restrict__ wih,
                                                 const float* __restrict__ whh,
                                                 const float* __restrict__ cosm,
                                                 const int* __restrict__ sup) {
    const int bid = blockIdx.x, tid = threadIdx.x;
    if (bid < 96) {
        int idx = bid * 512 + tid;
        int j = idx / 128, k = idx % 128;
        g_wT[0][k * 384 + j] = wih[idx];
        g_wT[1][k * 384 + j] = whh[idx];
    } else {
        __shared__ int ss[NSUP];
        if (tid < NSUP) ss[tid] = sup[tid];
        __syncthreads();
        int r = (bid - 96) * 512 + tid;
        if (r < NRELS) {
            float m = -3.4e38f;
            #pragma unroll
            for (int s = 0; s < NSUP; ++s)
                m = fmaxf(m, cosm[(long long)ss[s] * NRELS + r]);
            g_best[r] = m;
        }
    }
}

// K2: blocks [0,313): relgi; [313,323): rank; [323,579): expand0
__global__ void __launch_bounds__(512) k2_kernel(const float* __restrict__ rel_emb,
                                                 const float* __restrict__ b_ih,
                                                 const int2* __restrict__ edge,
                                                 const int* __restrict__ query_head,
                                                 float* __restrict__ out) {
    const int bid = blockIdx.x, tid = threadIdx.x;
    if (bid < 313) {
        // ---- relgi ----
        __shared__ __align__(16) float s_f[128 * SH];
        const int rb = bid * 16;
        for (int idx = tid; idx < 16 * 128; idx += 512) {
            int n = idx >> 7, d = idx & 127;
            int r = rb + n;
            s_f[d * SH + n] = (r < NRELS) ? rel_emb[r * 128 + d] : 0.f;
        }
        __syncthreads();
        if (tid < 384) {
            const int j = tid;
            const float bj = b_ih[j];
            ull acc[8];
            ull bj2 = f2pack(bj, bj);
            #pragma unroll
            for (int m = 0; m < 8; ++m) acc[m] = bj2;
            const float* wt = g_wT[0];
            #pragma unroll 4
            for (int k = 0; k < 128; ++k) {
                float w = __ldg(&wt[k * 384 + j]);
                ull wd = f2pack(w, w);
                const ulonglong2* row = (const ulonglong2*)&s_f[k * SH];
                ulonglong2 r0 = row[0], r1 = row[1], r2 = row[2], r3 = row[3];
                acc[0] = f2fma(wd, r0.x, acc[0]); acc[1] = f2fma(wd, r0.y, acc[1]);
                acc[2] = f2fma(wd, r1.x, acc[2]); acc[3] = f2fma(wd, r1.y, acc[3]);
                acc[4] = f2fma(wd, r2.x, acc[4]); acc[5] = f2fma(wd, r2.y, acc[5]);
                acc[6] = f2fma(wd, r3.x, acc[6]); acc[7] = f2fma(wd, r3.y, acc[7]);
            }
            #pragma unroll
            for (int m = 0; m < 8; ++m) {
                float2 v = *(float2*)&acc[m];
                int r0i = rb + 2 * m, r1i = rb + 2 * m + 1;
                if (r0i < NRELS) g_relgi[r0i * 384 + j] = v.x;
                if (r1i < NRELS) g_relgi[r1i * 384 + j] = v.y;
            }
        }
    } else if (bid < 323) {
        // ---- rank ----
        __shared__ __align__(16) float tile[512];
        const int r = (bid - 313) * 512 + tid;
        const float mine = (r < NRELS) ? g_best[r] : 3.4e38f;
        u32 cnt = 0;
        for (int base = 0; base < NRELS; base += 512) {
            int t = base + tid;
            tile[tid] = (t < NRELS) ? g_best[t] : -3.4e38f;
            __syncthreads();
            int lim = NRELS - base; if (lim > 512) lim = 512;
            #pragma unroll 8
            for (int u = 0; u < lim; ++u) cnt += (tile[u] > mine);
            __syncthreads();
        }
        if (r < NRELS) g_rank[r] = cnt;
    } else {
        // ---- expand0 ----
        __shared__ __align__(16) ull keys[128];
        __shared__ int s_ent;
        const int b = bid - 323;
        const int i = tid;
        if (i == 0) s_ent = query_head[b];
        __syncthreads();
        if (i < 128) {
            const int ent = s_ent;
            int2 pr = __ldg(&edge[(long long)ent * NEI + i]);
            ull mykey = ((ull)ord32(g_best[pr.y]) << 32) | (u32)(127 - i);
            keys[i] = mykey;
        }
        __syncthreads();
        if (i < 128) {
            const int ent = s_ent;
            int2 pr = __ldg(&edge[(long long)ent * NEI + i]);
            ull mykey = keys[i];
            int rank = 0;
            #pragma unroll 8
            for (int t = 0; t < 128; ++t) rank += (keys[t] > mykey);
            if (rank < TOPK) {
                int j = rank;
                int gidx = b * TOPK + j;
                g_e[0][gidx] = pr.x;
                g_r[0][gidx] = pr.y;
                g_p[0][gidx] = 0;
                out[OFF_TN + b * 192 + j] = (float)pr.x;
                out[OFF_PN + b * 192 + j] = (float)ent;
                out[OFF_PI + b * 192 + 128 + j] = (float)j;
            }
        }
    }
}

// K3: blocks [0,256): expand_big step1; [256,4352): gru1 flat
__global__ void __launch_bounds__(512) k3_kernel(const int2* __restrict__ edge,
                                                 const float* __restrict__ b_hh,
                                                 float* __restrict__ out) {
    const int bid = blockIdx.x;
    if (bid < 256) {
        expand_big_body(edge, out, 1, bid);
    } else {
        const int idx = (bid - 256) * 512 + threadIdx.x;
        const int d = idx & 127;
        const int k = (idx >> 7) & 63;
        const int b = idx >> 13;
        const int r = g_r[0][b * TOPK + k];
        const float* gi = &g_relgi[r * 384];
        float hr = b_hh[d], hz = b_hh[128 + d], hn = b_hh[256 + d];
        float rg = 1.f / (1.f + expf(-(gi[d] + hr)));
        float z  = 1.f / (1.f + expf(-(gi[128 + d] + hz)));
        float nn = tanhf(gi[256 + d] + rg * hn);
        out[OFF_TE + ((b * 3 + 0) * 64 + k) * 128 + d] = (1.f - z) * nn;
    }
}

// K4: blocks [0,256): expand_big step2; [256,1280): gru23 step1
__global__ void __launch_bounds__(512) k4_kernel(const int2* __restrict__ edge,
                                                 const float* __restrict__ b_hh,
                                                 float* __restrict__ out) {
    const int bid = blockIdx.x;
    if (bid < 256) {
        expand_big_body(edge, out, 2, bid);
    } else {
        const int g = bid - 256;
        gru23_body(b_hh, out, 1, g >> 2, (g & 3) * 16);
    }
}

// K5: gru23 step2
__global__ void __launch_bounds__(512) k5_kernel(const float* __restrict__ b_hh,
                                                 float* __restrict__ out) {
    const int g = blockIdx.x;
    gru23_body(b_hh, out, 2, g >> 2, (g & 3) * 16);
}

// ================= launch =====================================================
extern "C" void kernel_launch(void* const* d_in, const int* in_sizes, int n_in,
                              void* d_out, int out_size) {
    (void)in_sizes; (void)n_in; (void)out_size;
    const int*   qh      = (const int*)d_in[0];
    const int2*  edge    = (const int2*)d_in[1];
    const int*   sup     = (const int*)d_in[2];
    const float* cosm    = (const float*)d_in[3];
    const float* rel_emb = (const float*)d_in[4];
    const float* wih     = (const float*)d_in[5];
    const float* whh     = (const float*)d_in[6];
    const float* bih     = (const float*)d_in[7];
    const float* bhh     = (const float*)d_in[8];
    float* out = (float*)d_out;

    k1_kernel<<<106, 512>>>(wih, whh, cosm, sup);
    k2_kernel<<<579, 512>>>(rel_emb, bih, edge, qh, out);
    k3_kernel<<<4352, 512>>>(edge, bhh, out);
    k4_kernel<<<1280, 512>>>(edge, bhh, out);
    k5_kernel<<<1024, 512>>>(bhh, out);
}

// round 7
// speedup vs baseline: 1.1369x; 1.1369x over previous
#include <cuda_runtime.h>
#include <cuda_bf16.h>
#include <math.h>

#define BATCH   256
#define NEI     128
#define NRELS   5000
#define NSUP    32
#define DIM     128
#define TOPK    64
#define NCAND   8192

#define OFF_TN  0
#define OFF_TE  49152
#define OFF_PI  6340608
#define OFF_PN  6389760
#define OFF_AR  6438912

typedef unsigned long long ull;
typedef unsigned int u32;

__device__ float g_best[NRELS];
__device__ u32   g_rank[NRELS];
__device__ float g_relgi[NRELS * 384];
__device__ float g_wT[2][128 * 384];
__device__ int   g_e[3][BATCH * TOPK];
__device__ int   g_r[3][BATCH * TOPK];
__device__ int   g_p[3][BATCH * TOPK];

__device__ __forceinline__ ull f2pack(float lo, float hi) {
    ull d; asm("mov.b64 %0, {%1, %2};" : "=l"(d) : "f"(lo), "f"(hi)); return d;
}
__device__ __forceinline__ ull f2fma(ull a, ull b, ull c) {
    ull d; asm("fma.rn.f32x2 %0, %1, %2, %3;" : "=l"(d) : "l"(a), "l"(b), "l"(c)); return d;
}
__device__ __forceinline__ u32 ord32(float s) {
    u32 u = __float_as_uint(s);
    return (u & 0x80000000u) ? ~u : (u | 0x80000000u);
}
__device__ __forceinline__ float sigf(float x) { return 1.f / (1.f + __expf(-x)); }
__device__ __forceinline__ float tanhfast(float x) {
    float e = __expf(2.f * x);
    return 1.f - 2.f / (e + 1.f);
}

#define SHN 20   // padded [k][n] row stride: 80B, 16B-aligned, de-conflicted

// ================= expand_big body (512 threads) =============================
__device__ __forceinline__ void expand_big_body(const int2* __restrict__ edge,
                                                float* __restrict__ out,
                                                int step, int b) {
    __shared__ int s_cur[TOPK];
    __shared__ u32 s_p13[16], s_q13[16];
    __shared__ u32 s_bp, s_bq;
    __shared__ u32 wkeys[TOPK];
    __shared__ u32 s_wn;

    const int tid = threadIdx.x;
    const int wid = tid >> 5, lane = tid & 31;

    if (tid < TOPK) s_cur[tid] = g_e[step - 1][b * TOPK + tid];
    if (tid == 0) s_wn = 0;
    __syncthreads();

    u32 myk[16];
    #pragma unroll
    for (int m = 0; m < 16; ++m) {
        int i = tid + m * 512;
        int c = i >> 7, n = i & 127;
        int2 pr = __ldg(&edge[(long long)s_cur[c] * NEI + n]);
        myk[m] = (g_rank[pr.y] << 13) | (u32)i;
    }

    u32 K = 0;
    #pragma unroll 1
    for (int shift = 24; shift >= 0; shift -= 2) {
        u32 X1 = K | (1u << shift), X2 = K | (2u << shift), X3 = K | (3u << shift);
        u32 c1 = 0, c2 = 0, c3 = 0;
        #pragma unroll
        for (int m = 0; m < 16; ++m) {
            u32 k0 = myk[m];
            c1 += (k0 < X1); c2 += (k0 < X2); c3 += (k0 < X3);
        }
        u32 p = c1 | (c2 << 16);
        u32 q = c3;
        p = __reduce_add_sync(0xffffffffu, p);
        q = __reduce_add_sync(0xffffffffu, q);
        if (lane == 0) { s_p13[wid] = p; s_q13[wid] = q; }
        __syncthreads();
        if (tid < 32) {
            u32 vp = (tid < 16) ? s_p13[tid] : 0u;
            u32 vq = (tid < 16) ? s_q13[tid] : 0u;
            vp = __reduce_add_sync(0xffffffffu, vp);
            vq = __reduce_add_sync(0xffffffffu, vq);
            if (tid == 0) { s_bp = vp; s_bq = vq; }
        }
        __syncthreads();
        u32 n1 = s_bp & 0xffffu, n2 = s_bp >> 16, n3 = s_bq;
        u32 t = (n1 < TOPK) ? ((n2 < TOPK) ? ((n3 < TOPK) ? 3u : 2u) : 1u) : 0u;
        K |= t << shift;
        __syncthreads();
    }

    #pragma unroll
    for (int m = 0; m < 16; ++m) {
        if (myk[m] <= K) {
            u32 p = atomicAdd(&s_wn, 1u);
            wkeys[p] = myk[m];
        }
    }
    __syncthreads();

    if (tid < TOPK) {
        u32 my = wkeys[tid];
        int rank = 0;
        #pragma unroll 8
        for (int t = 0; t < TOPK; ++t) rank += (wkeys[t] < my);
        int i = my & (NCAND - 1);
        int c = i >> 7, n = i & 127;
        int ent = s_cur[c];
        int2 pr = __ldg(&edge[(long long)ent * NEI + n]);
        int j = rank;
        int gidx = b * TOPK + j;
        g_e[step][gidx] = pr.x;
        g_r[step][gidx] = pr.y;
        g_p[step][gidx] = c;
        out[OFF_TN + b * 192 + step * 64 + j] = (float)pr.x;
        if (step == 1) {
            out[OFF_PI + b * 192 + j]       = (float)c;
            out[OFF_PN + b * 192 + 64 + j]  = (float)g_e[0][b * TOPK + c];
            out[OFF_AR + b * 192 + j]       = (float)g_r[0][b * TOPK + c];
        } else {
            out[OFF_PI + b * 192 + 64 + j]  = (float)c;
            out[OFF_PN + b * 192 + 128 + j] = (float)g_e[1][b * TOPK + c];
            out[OFF_AR + b * 192 + 64 + j]  = (float)g_r[1][b * TOPK + c];
            out[OFF_AR + b * 192 + 128 + j] = (float)pr.y;
        }
    }
}

// ================= K1: prep_w || best ========================================
__global__ void __launch_bounds__(512) k1_kernel(const float* __restrict__ wih,
                                                 const float* __restrict__ whh,
                                                 const float* __restrict__ cosm,
                                                 const int* __restrict__ sup) {
    const int bid = blockIdx.x, tid = threadIdx.x;
    if (bid < 96) {
        int idx = bid * 512 + tid;
        int j = idx / 128, k = idx % 128;
        g_wT[0][k * 384 + j] = wih[idx];
        g_wT[1][k * 384 + j] = whh[idx];
    } else {
        __shared__ int ss[NSUP];
        if (tid < NSUP) ss[tid] = sup[tid];
        __syncthreads();
        int r = (bid - 96) * 512 + tid;
        if (r < NRELS) {
            float m = -3.4e38f;
            #pragma unroll
            for (int s = 0; s < NSUP; ++s)
                m = fmaxf(m, cosm[(long long)ss[s] * NRELS + r]);
            g_best[r] = m;
        }
    }
}

// ================= 3-gate matvec core (128 threads, 16 rows) =================
// s_x: [k][n] layout, stride SHN. Thread d owns gate rows {d, 128+d, 256+d}.
// Accumulators arrive pre-loaded with bias. wsel: 0=W_ih, 1=W_hh.
__device__ __forceinline__ void matvec3(const float* __restrict__ s_x, int wsel,
                                        int d, ull* aR, ull* aZ, ull* aN) {
    const float* wt = g_wT[wsel];
    #pragma unroll 2
    for (int k = 0; k < 128; ++k) {
        float wr = __ldg(&wt[k * 384 + d]);
        float wz = __ldg(&wt[k * 384 + 128 + d]);
        float wn = __ldg(&wt[k * 384 + 256 + d]);
        ull wr2 = f2pack(wr, wr), wz2 = f2pack(wz, wz), wn2 = f2pack(wn, wn);
        const ulonglong2* row = (const ulonglong2*)&s_x[k * SHN];
        ulonglong2 h0 = row[0], h1 = row[1], h2 = row[2], h3 = row[3];
        aR[0] = f2fma(wr2, h0.x, aR[0]); aR[1] = f2fma(wr2, h0.y, aR[1]);
        aR[2] = f2fma(wr2, h1.x, aR[2]); aR[3] = f2fma(wr2, h1.y, aR[3]);
        aR[4] = f2fma(wr2, h2.x, aR[4]); aR[5] = f2fma(wr2, h2.y, aR[5]);
        aR[6] = f2fma(wr2, h3.x, aR[6]); aR[7] = f2fma(wr2, h3.y, aR[7]);
        aZ[0] = f2fma(wz2, h0.x, aZ[0]); aZ[1] = f2fma(wz2, h0.y, aZ[1]);
        aZ[2] = f2fma(wz2, h1.x, aZ[2]); aZ[3] = f2fma(wz2, h1.y, aZ[3]);
        aZ[4] = f2fma(wz2, h2.x, aZ[4]); aZ[5] = f2fma(wz2, h2.y, aZ[5]);
        aZ[6] = f2fma(wz2, h3.x, aZ[6]); aZ[7] = f2fma(wz2, h3.y, aZ[7]);
        aN[0] = f2fma(wn2, h0.x, aN[0]); aN[1] = f2fma(wn2, h0.y, aN[1]);
        aN[2] = f2fma(wn2, h1.x, aN[2]); aN[3] = f2fma(wn2, h1.y, aN[3]);
        aN[4] = f2fma(wn2, h2.x, aN[4]); aN[5] = f2fma(wn2, h2.y, aN[5]);
        aN[6] = f2fma(wn2, h3.x, aN[6]); aN[7] = f2fma(wn2, h3.y, aN[7]);
    }
}

// ================= K2: relgi_b || rank || expand0  (128-thread blocks) =======
__global__ void __launch_bounds__(128) k2_kernel(const float* __restrict__ rel_emb,
                                                 const float* __restrict__ b_ih,
                                                 const int2* __restrict__ edge,
                                                 const int* __restrict__ query_head,
                                                 float* __restrict__ out) {
    const int bid = blockIdx.x, tid = threadIdx.x;
    if (bid < 313) {
        // ---- relgi: gi = rel_emb @ W_ih^T + b_ih, 16 rels per block ----
        __shared__ __align__(16) float s_x[128 * SHN];
        const int rb = bid * 16;
        const int d = tid;
        #pragma unroll
        for (int n = 0; n < 16; ++n) {
            int r = rb + n;
            s_x[d * SHN + n] = (r < NRELS) ? __ldg(&rel_emb[r * 128 + d]) : 0.f;
        }
        __syncthreads();
        ull aR[8], aZ[8], aN[8];
        float br = b_ih[d], bz = b_ih[128 + d], bn = b_ih[256 + d];
        #pragma unroll
        for (int m = 0; m < 8; ++m) {
            aR[m] = f2pack(br, br); aZ[m] = f2pack(bz, bz); aN[m] = f2pack(bn, bn);
        }
        matvec3(s_x, 0, d, aR, aZ, aN);
        #pragma unroll
        for (int m = 0; m < 8; ++m) {
            float2 vr = *(float2*)&aR[m], vz = *(float2*)&aZ[m], vn = *(float2*)&aN[m];
            int r0 = rb + 2 * m, r1 = r0 + 1;
            if (r0 < NRELS) {
                g_relgi[r0 * 384 + d] = vr.x;
                g_relgi[r0 * 384 + 128 + d] = vz.x;
                g_relgi[r0 * 384 + 256 + d] = vn.x;
            }
            if (r1 < NRELS) {
                g_relgi[r1 * 384 + d] = vr.y;
                g_relgi[r1 * 384 + 128 + d] = vz.y;
                g_relgi[r1 * 384 + 256 + d] = vn.y;
            }
        }
    } else if (bid < 353) {
        // ---- rank ----
        __shared__ float tile[128];
        const int r = (bid - 313) * 128 + tid;
        const float mine = (r < NRELS) ? g_best[r] : 3.4e38f;
        u32 cnt = 0;
        for (int base = 0; base < NRELS; base += 128) {
            int t = base + tid;
            tile[tid] = (t < NRELS) ? g_best[t] : -3.4e38f;
            __syncthreads();
            int lim = NRELS - base; if (lim > 128) lim = 128;
            #pragma unroll 8
            for (int u = 0; u < lim; ++u) cnt += (tile[u] > mine);
            __syncthreads();
        }
        if (r < NRELS) g_rank[r] = cnt;
    } else {
        // ---- expand0 ----
        __shared__ __align__(16) ull keys[128];
        __shared__ int s_ent;
        const int b = bid - 353;
        const int i = tid;
        if (i == 0) s_ent = query_head[b];
        __syncthreads();
        const int ent = s_ent;
        int2 pr = __ldg(&edge[(long long)ent * NEI + i]);
        ull mykey = ((ull)ord32(g_best[pr.y]) << 32) | (u32)(127 - i);
        keys[i] = mykey;
        __syncthreads();
        int rank = 0;
        #pragma unroll 8
        for (int t = 0; t < 128; ++t) rank += (keys[t] > mykey);
        if (rank < TOPK) {
            int j = rank;
            int gidx = b * TOPK + j;
            g_e[0][gidx] = pr.x;
            g_r[0][gidx] = pr.y;
            g_p[0][gidx] = 0;
            out[OFF_TN + b * 192 + j] = (float)pr.x;
            out[OFF_PN + b * 192 + j] = (float)ent;
            out[OFF_PI + b * 192 + 128 + j] = (float)j;
        }
    }
}

// ================= K3: expand_big(1) || gru1 (512-thread blocks) =============
__global__ void __launch_bounds__(512) k3_kernel(const int2* __restrict__ edge,
                                                 const float* __restrict__ b_hh,
                                                 float* __restrict__ out) {
    const int bid = blockIdx.x;
    if (bid < 256) {
        expand_big_body(edge, out, 1, bid);
    } else {
        const int idx = (bid - 256) * 512 + threadIdx.x;
        const int d = idx & 127;
        const int k = (idx >> 7) & 63;
        const int b = idx >> 13;
        const int r = g_r[0][b * TOPK + k];
        const float* gi = &g_relgi[r * 384];
        float hr = b_hh[d], hz = b_hh[128 + d], hn = b_hh[256 + d];
        float rg = sigf(gi[d] + hr);
        float z  = sigf(gi[128 + d] + hz);
        float nn = tanhfast(gi[256 + d] + rg * hn);
        out[OFF_TE + ((b * 3 + 0) * 64 + k) * 128 + d] = (1.f - z) * nn;
    }
}

// ================= expand_big standalone =====================================
__global__ void __launch_bounds__(512) xbig_kernel(const int2* __restrict__ edge,
                                                   float* __restrict__ out, int step) {
    expand_big_body(edge, out, step, blockIdx.x);
}

// ================= gru23b: 3-gate fused matvec + epilogue ====================
__global__ void __launch_bounds__(128) gru23b_kernel(const float* __restrict__ b_hh,
                                                     float* __restrict__ out, int step) {
    const int b = blockIdx.y;
    const int kb = blockIdx.x * 16;
    const int d = threadIdx.x;
    __shared__ __align__(16) float s_h[128 * SHN];   // [k][n]
    __shared__ int s_p[16], s_rel[16];
    if (d < 16) {
        s_p[d]   = g_p[step][b * TOPK + kb + d];
        s_rel[d] = g_r[step][b * TOPK + kb + d];
    }
    __syncthreads();
    const float* te_prev = &out[OFF_TE + (b * 3 + (step - 1)) * 64 * 128];
    #pragma unroll
    for (int n = 0; n < 16; ++n)
        s_h[d * SHN + n] = te_prev[s_p[n] * 128 + d];
    __syncthreads();

    ull aR[8], aZ[8], aN[8];
    float br = b_hh[d], bz = b_hh[128 + d], bn = b_hh[256 + d];
    #pragma unroll
    for (int m = 0; m < 8; ++m) {
        aR[m] = f2pack(br, br); aZ[m] = f2pack(bz, bz); aN[m] = f2pack(bn, bn);
    }
    matvec3(s_h, 1, d, aR, aZ, aN);

    float* te_out = &out[OFF_TE + ((b * 3 + step) * 64 + kb) * 128];
    #pragma unroll
    for (int m = 0; m < 8; ++m) {
        float2 vr = *(float2*)&aR[m], vz = *(float2*)&aZ[m], vn = *(float2*)&aN[m];
        #pragma unroll
        for (int s = 0; s < 2; ++s) {
            int n = 2 * m + s;
            float hr = s ? vr.y : vr.x;
            float hz = s ? vz.y : vz.x;
            float hn = s ? vn.y : vn.x;
            int rel = s_rel[n];
            const float* gi = &g_relgi[rel * 384];
            float hprev = s_h[d * SHN + n];
            float rg = sigf(gi[d] + hr);
            float z  = sigf(gi[128 + d] + hz);
            float nn = tanhfast(gi[256 + d] + rg * hn);
            te_out[n * 128 + d] = (1.f - z) * nn + z * hprev;
        }
    }
}

// ================= launch =====================================================
extern "C" void kernel_launch(void* const* d_in, const int* in_sizes, int n_in,
                              void* d_out, int out_size) {
    (void)in_sizes; (void)n_in; (void)out_size;
    const int*   qh      = (const int*)d_in[0];
    const int2*  edge    = (const int2*)d_in[1];
    const int*   sup     = (const int*)d_in[2];
    const float* cosm    = (const float*)d_in[3];
    const float* rel_emb = (const float*)d_in[4];
    const float* wih     = (const float*)d_in[5];
    const float* whh     = (const float*)d_in[6];
    const float* bih     = (const float*)d_in[7];
    const float* bhh     = (const float*)d_in[8];
    float* out = (float*)d_out;

    k1_kernel<<<106, 512>>>(wih, whh, cosm, sup);
    k2_kernel<<<609, 128>>>(rel_emb, bih, edge, qh, out);
    k3_kernel<<<4352, 512>>>(edge, bhh, out);
    gru23b_kernel<<<dim3(4, BATCH), 128>>>(bhh, out, 1);
    xbig_kernel<<<BATCH, 512>>>(edge, out, 2);
    gru23b_kernel<<<dim3(4, BATCH), 128>>>(bhh, out, 2);
}